// round 1
// baseline (speedup 1.0000x reference)
#include <cuda_runtime.h>
#include <math.h>

#define NNB  16
#define NOB  8
#define SDIM 4
#define H1   64
#define ED   16
#define HP   64
#define XC   85   // 1 + SD + SD*NN + 2*NO = 1+4+64+16

__global__ void __launch_bounds__(256)
bnet_kernel(const float* __restrict__ x,
            const float* __restrict__ Wp1n, const float* __restrict__ bp1n,
            const float* __restrict__ Wp2n, const float* __restrict__ bp2n,
            const float* __restrict__ Wr1n, const float* __restrict__ br1n,
            const float* __restrict__ Wr2n, const float* __restrict__ br2n,
            const float* __restrict__ Wp1o, const float* __restrict__ bp1o,
            const float* __restrict__ Wp2o, const float* __restrict__ bp2o,
            const float* __restrict__ Wr1o, const float* __restrict__ br1o,
            const float* __restrict__ Wr2o, const float* __restrict__ br2o,
            const float* __restrict__ Wpsi1, const float* __restrict__ bpsi1,
            const float* __restrict__ Wpsi2, const float* __restrict__ bpsi2,
            float* __restrict__ out, int nb)
{
    __shared__ __align__(16) float sWp1n[SDIM*H1];
    __shared__ __align__(16) float sbp1n[H1];
    __shared__ __align__(16) float sWp2n[H1*ED];
    __shared__ __align__(16) float sbp2n[ED];
    __shared__ __align__(16) float sWr1n[ED*H1];
    __shared__ __align__(16) float sbr1n[H1];
    __shared__ __align__(16) float sWr2n[H1*ED];
    __shared__ __align__(16) float sbr2n[ED];
    __shared__ __align__(16) float sWp1o[2*H1];
    __shared__ __align__(16) float sbp1o[H1];
    __shared__ __align__(16) float sWp2o[H1*ED];
    __shared__ __align__(16) float sbp2o[ED];
    __shared__ __align__(16) float sWr1o[ED*H1];
    __shared__ __align__(16) float sbr1o[H1];
    __shared__ __align__(16) float sWr2o[H1*ED];
    __shared__ __align__(16) float sbr2o[ED];
    __shared__ __align__(16) float sWpsi1[(2*ED+SDIM)*HP];
    __shared__ __align__(16) float sbpsi1[HP];
    __shared__ __align__(16) float sWpsi2[HP*2];
    __shared__ __align__(16) float sbpsi2[2];

    // ---- cooperative weight staging ----
    {
        float* dsts[20]       = { sWp1n, sbp1n, sWp2n, sbp2n, sWr1n, sbr1n, sWr2n, sbr2n,
                                  sWp1o, sbp1o, sWp2o, sbp2o, sWr1o, sbr1o, sWr2o, sbr2o,
                                  sWpsi1, sbpsi1, sWpsi2, sbpsi2 };
        const float* srcs[20] = { Wp1n, bp1n, Wp2n, bp2n, Wr1n, br1n, Wr2n, br2n,
                                  Wp1o, bp1o, Wp2o, bp2o, Wr1o, br1o, Wr2o, br2o,
                                  Wpsi1, bpsi1, Wpsi2, bpsi2 };
        const int ns[20]      = { SDIM*H1, H1, H1*ED, ED, ED*H1, H1, H1*ED, ED,
                                  2*H1,    H1, H1*ED, ED, ED*H1, H1, H1*ED, ED,
                                  (2*ED+SDIM)*HP, HP, HP*2, 2 };
        for (int a = 0; a < 20; ++a)
            for (int i = threadIdx.x; i < ns[a]; i += blockDim.x)
                dsts[a][i] = srcs[a][i];
    }
    __syncthreads();

    const int t = blockIdx.x * blockDim.x + threadIdx.x;
    if (t >= nb) return;
    const float* row = x + (size_t)t * XC;

    const float g0 = row[1], g1 = row[2], g2 = row[3], g3 = row[4];

    float hs[H1];
    float bx = 0.f, by = 0.f;

    // ======================= neighbor deep-set =======================
    #pragma unroll
    for (int h = 0; h < H1; ++h) hs[h] = 0.f;

    #pragma unroll 1
    for (int j = 0; j < NNB; ++j) {
        const float e0 = row[1+SDIM + 4*j + 0];
        const float e1 = row[1+SDIM + 4*j + 1];
        const float e2 = row[1+SDIM + 4*j + 2];
        const float e3 = row[1+SDIM + 4*j + 3];
        // barrier term on first two coords, P = -e
        {
            const float px = -e0, py = -e1;
            const float q  = fmaf(px, px, py*py);
            const float rq = rsqrtf(q);
            const float nrm = q * rq;                 // sqrt(q)
            const float s  = 0.05f * __fdividef(1.0f, nrm * (nrm - 0.3f));
            bx = fmaf(s, px, bx);
            by = fmaf(s, py, by);
        }
        #pragma unroll
        for (int h = 0; h < H1; ++h) {
            float v = sbp1n[h];
            v = fmaf(e0, sWp1n[0*H1 + h], v);
            v = fmaf(e1, sWp1n[1*H1 + h], v);
            v = fmaf(e2, sWp1n[2*H1 + h], v);
            v = fmaf(e3, sWp1n[3*H1 + h], v);
            hs[h] += fmaxf(v, 0.f);
        }
    }

    float sp[ED];
    #pragma unroll
    for (int o = 0; o < ED; ++o) sp[o] = (float)NNB * sbp2n[o];
    #pragma unroll
    for (int h = 0; h < H1; ++h) {
        const float v = hs[h];
        #pragma unroll
        for (int o = 0; o < ED; ++o) sp[o] = fmaf(v, sWp2n[h*ED + o], sp[o]);
    }
    // rho_n = relu(sp@Wr1n+br1n) @ Wr2n + br2n
    #pragma unroll
    for (int h = 0; h < H1; ++h) hs[h] = sbr1n[h];
    #pragma unroll
    for (int i = 0; i < ED; ++i) {
        const float v = sp[i];
        #pragma unroll
        for (int h = 0; h < H1; ++h) hs[h] = fmaf(v, sWr1n[i*H1 + h], hs[h]);
    }
    float rn[ED];
    #pragma unroll
    for (int o = 0; o < ED; ++o) rn[o] = sbr2n[o];
    #pragma unroll
    for (int h = 0; h < H1; ++h) {
        const float v = fmaxf(hs[h], 0.f);
        #pragma unroll
        for (int o = 0; o < ED; ++o) rn[o] = fmaf(v, sWr2n[h*ED + o], rn[o]);
    }

    // ======================= obstacle deep-set =======================
    #pragma unroll
    for (int h = 0; h < H1; ++h) hs[h] = 0.f;

    #pragma unroll 1
    for (int j = 0; j < NOB; ++j) {
        const float e0 = row[1+SDIM+SDIM*NNB + 2*j + 0];
        const float e1 = row[1+SDIM+SDIM*NNB + 2*j + 1];
        {
            const float px = -e0, py = -e1;
            const float q  = fmaf(px, px, py*py);
            const float rq = rsqrtf(q);
            const float nrm = q * rq;
            const float s  = 0.05f * __fdividef(1.0f, nrm * (nrm - 0.3f));
            bx = fmaf(s, px, bx);
            by = fmaf(s, py, by);
        }
        #pragma unroll
        for (int h = 0; h < H1; ++h) {
            float v = sbp1o[h];
            v = fmaf(e0, sWp1o[0*H1 + h], v);
            v = fmaf(e1, sWp1o[1*H1 + h], v);
            hs[h] += fmaxf(v, 0.f);
        }
    }

    #pragma unroll
    for (int o = 0; o < ED; ++o) sp[o] = (float)NOB * sbp2o[o];
    #pragma unroll
    for (int h = 0; h < H1; ++h) {
        const float v = hs[h];
        #pragma unroll
        for (int o = 0; o < ED; ++o) sp[o] = fmaf(v, sWp2o[h*ED + o], sp[o]);
    }
    #pragma unroll
    for (int h = 0; h < H1; ++h) hs[h] = sbr1o[h];
    #pragma unroll
    for (int i = 0; i < ED; ++i) {
        const float v = sp[i];
        #pragma unroll
        for (int h = 0; h < H1; ++h) hs[h] = fmaf(v, sWr1o[i*H1 + h], hs[h]);
    }
    float ro[ED];
    #pragma unroll
    for (int o = 0; o < ED; ++o) ro[o] = sbr2o[o];
    #pragma unroll
    for (int h = 0; h < H1; ++h) {
        const float v = fmaxf(hs[h], 0.f);
        #pragma unroll
        for (int o = 0; o < ED; ++o) ro[o] = fmaf(v, sWr2o[h*ED + o], ro[o]);
    }

    // ======================= psi head =======================
    #pragma unroll
    for (int h = 0; h < HP; ++h) hs[h] = sbpsi1[h];
    #pragma unroll
    for (int i = 0; i < ED; ++i) {
        const float v = rn[i];
        #pragma unroll
        for (int h = 0; h < HP; ++h) hs[h] = fmaf(v, sWpsi1[i*HP + h], hs[h]);
    }
    #pragma unroll
    for (int i = 0; i < ED; ++i) {
        const float v = ro[i];
        #pragma unroll
        for (int h = 0; h < HP; ++h) hs[h] = fmaf(v, sWpsi1[(ED+i)*HP + h], hs[h]);
    }
    #pragma unroll
    for (int h = 0; h < HP; ++h) {
        float v = hs[h];
        v = fmaf(g0, sWpsi1[(2*ED+0)*HP + h], v);
        v = fmaf(g1, sWpsi1[(2*ED+1)*HP + h], v);
        v = fmaf(g2, sWpsi1[(2*ED+2)*HP + h], v);
        v = fmaf(g3, sWpsi1[(2*ED+3)*HP + h], v);
        hs[h] = fmaxf(v, 0.f);
    }
    float a0 = sbpsi2[0], a1 = sbpsi2[1];
    #pragma unroll
    for (int h = 0; h < HP; ++h) {
        a0 = fmaf(hs[h], sWpsi2[2*h + 0], a0);
        a1 = fmaf(hs[h], sWpsi2[2*h + 1], a1);
    }

    // emp = (tanh+1)/2*(PHI_MAX-PHI_MIN)+PHI_MIN = 2*tanh
    a0 = fmaf(2.0f, tanhf(a0), bx);
    a1 = fmaf(2.0f, tanhf(a1), by);

    const float inv = fmaxf(fmaxf(fabsf(a0), fabsf(a1)) * 0.5f, 1.0f);
    const float r   = __fdividef(1.0f, inv);
    float2 res;
    res.x = a0 * r;
    res.y = a1 * r;
    reinterpret_cast<float2*>(out)[t] = res;
}

extern "C" void kernel_launch(void* const* d_in, const int* in_sizes, int n_in,
                              void* d_out, int out_size) {
    const float* x     = (const float*)d_in[0];
    const float* Wp1n  = (const float*)d_in[1];
    const float* bp1n  = (const float*)d_in[2];
    const float* Wp2n  = (const float*)d_in[3];
    const float* bp2n  = (const float*)d_in[4];
    const float* Wr1n  = (const float*)d_in[5];
    const float* br1n  = (const float*)d_in[6];
    const float* Wr2n  = (const float*)d_in[7];
    const float* br2n  = (const float*)d_in[8];
    const float* Wp1o  = (const float*)d_in[9];
    const float* bp1o  = (const float*)d_in[10];
    const float* Wp2o  = (const float*)d_in[11];
    const float* bp2o  = (const float*)d_in[12];
    const float* Wr1o  = (const float*)d_in[13];
    const float* br1o  = (const float*)d_in[14];
    const float* Wr2o  = (const float*)d_in[15];
    const float* br2o  = (const float*)d_in[16];
    const float* Wpsi1 = (const float*)d_in[17];
    const float* bpsi1 = (const float*)d_in[18];
    const float* Wpsi2 = (const float*)d_in[19];
    const float* bpsi2 = (const float*)d_in[20];
    float* out = (float*)d_out;

    const int nb = in_sizes[0] / XC;
    const int threads = 256;
    const int blocks = (nb + threads - 1) / threads;
    bnet_kernel<<<blocks, threads>>>(x,
        Wp1n, bp1n, Wp2n, bp2n, Wr1n, br1n, Wr2n, br2n,
        Wp1o, bp1o, Wp2o, bp2o, Wr1o, br1o, Wr2o, br2o,
        Wpsi1, bpsi1, Wpsi2, bpsi2, out, nb);
}